// round 5
// baseline (speedup 1.0000x reference)
#include <cuda_runtime.h>
#include <math.h>

#define N_NODES 50000
#define N_EDGES 400000
#define HEADS 8
#define HID 32
#define F 256            // HEADS*HID
#define NEG 0.2f

// ---------------- scratch (device globals: allocation-free) ----------------
__device__ float g_h[N_NODES * F];        // X @ W (pre-attention features)
__device__ float g_x[N_NODES * F];        // layer output
__device__ float g_asrc[N_NODES * HEADS];
__device__ float g_adst[N_NODES * HEADS];
__device__ float g_p[N_NODES * 64];       // [P_a | P_b] node projections
__device__ float g_wcat[256 * 64];        // [Wp1_a | Wp1_b] packed
__device__ int   g_cnt[N_NODES];
__device__ int   g_off[N_NODES + 1];
__device__ int   g_fill[N_NODES];
__device__ int   g_bsum[256];
__device__ int   g_csrc[N_EDGES];

__device__ __forceinline__ float leaky(float x) { return x > 0.f ? x : NEG * x; }

__device__ __forceinline__ unsigned f2tf(float f) {
    unsigned r;
    asm("cvt.rna.tf32.f32 %0, %1;" : "=r"(r) : "f"(f));
    return r;
}

__device__ __forceinline__ void mma8(float* c,
    unsigned a0, unsigned a1, unsigned a2, unsigned a3,
    unsigned b0, unsigned b1)
{
    asm volatile(
        "mma.sync.aligned.m16n8k8.row.col.f32.tf32.tf32.f32 "
        "{%0,%1,%2,%3}, {%4,%5,%6,%7}, {%8,%9}, {%0,%1,%2,%3};"
        : "+f"(c[0]), "+f"(c[1]), "+f"(c[2]), "+f"(c[3])
        : "r"(a0), "r"(a1), "r"(a2), "r"(a3), "r"(b0), "r"(b1));
}

// ------- 3xTF32 split GEMM: C[M x N] = A[M x K] @ B[K x N], N tile 64 ------
// 256 threads = 8 warps (4 warp_m x 2 warp_n), warp tile 32x32.
// Split: a = hi + lo (tf32 each); C = Ah Bh + Al Bh + Ah Bl  (~fp32 accurate)
// Optional fused epilogue: per-row attention dots (2 heads per block tile).
__global__ __launch_bounds__(256) void tc_gemm_kernel(
    const float* __restrict__ A, const float* __restrict__ B,
    float* __restrict__ C, int M, int K, int ldb, int ldc,
    const float* __restrict__ a_src, const float* __restrict__ a_dst)
{
    __shared__ unsigned Ah[16][132], Al[16][132];
    __shared__ unsigned Bh[16][68],  Bl[16][68];
    __shared__ float sAs[64], sAd[64];

    const int tid = threadIdx.x;
    const int lane = tid & 31;
    const int wid = tid >> 5;
    const int warp_m = wid >> 1;          // 0..3  -> rows warp_m*32
    const int warp_n = wid & 1;           // 0..1  -> cols warp_n*32
    const int tig = lane & 3;             // k / col-pair index
    const int grp = lane >> 2;            // 0..7
    const int m0 = blockIdx.x * 128;
    const int n0 = blockIdx.y * 64;

    if (a_src != nullptr && tid < 64) {
        sAs[tid] = a_src[n0 + tid];
        sAd[tid] = a_dst[n0 + tid];
    }

    float acc[2][4][4];
#pragma unroll
    for (int mf = 0; mf < 2; ++mf)
#pragma unroll
        for (int nf = 0; nf < 4; ++nf)
#pragma unroll
            for (int j = 0; j < 4; ++j) acc[mf][nf][j] = 0.f;

    for (int k0 = 0; k0 < K; k0 += 16) {
        // A tile: 128x16 -> hi/lo, stored [k][m]
#pragma unroll
        for (int jj = 0; jj < 2; ++jj) {
            int f = tid + jj * 256;
            int m = f >> 2;
            int kq = (f & 3) * 4;
            float4 v = make_float4(0.f, 0.f, 0.f, 0.f);
            if (m0 + m < M)
                v = *(const float4*)&A[(size_t)(m0 + m) * K + k0 + kq];
            unsigned h;
            h = f2tf(v.x); Ah[kq + 0][m] = h; Al[kq + 0][m] = f2tf(v.x - __uint_as_float(h));
            h = f2tf(v.y); Ah[kq + 1][m] = h; Al[kq + 1][m] = f2tf(v.y - __uint_as_float(h));
            h = f2tf(v.z); Ah[kq + 2][m] = h; Al[kq + 2][m] = f2tf(v.z - __uint_as_float(h));
            h = f2tf(v.w); Ah[kq + 3][m] = h; Al[kq + 3][m] = f2tf(v.w - __uint_as_float(h));
        }
        // B tile: 16x64 -> hi/lo, stored [k][n]
        {
            int kk = tid >> 4;
            int nq = (tid & 15) * 4;
            float4 v = *(const float4*)&B[(size_t)(k0 + kk) * ldb + n0 + nq];
            unsigned h;
            h = f2tf(v.x); Bh[kk][nq + 0] = h; Bl[kk][nq + 0] = f2tf(v.x - __uint_as_float(h));
            h = f2tf(v.y); Bh[kk][nq + 1] = h; Bl[kk][nq + 1] = f2tf(v.y - __uint_as_float(h));
            h = f2tf(v.z); Bh[kk][nq + 2] = h; Bl[kk][nq + 2] = f2tf(v.z - __uint_as_float(h));
            h = f2tf(v.w); Bh[kk][nq + 3] = h; Bl[kk][nq + 3] = f2tf(v.w - __uint_as_float(h));
        }
        __syncthreads();
#pragma unroll
        for (int ks = 0; ks < 2; ++ks) {
            const int k = ks * 8;
            // A fragments (hi & lo) for 2 m16 frags
            unsigned ah[2][4], al[2][4];
#pragma unroll
            for (int mf = 0; mf < 2; ++mf) {
                int mb = warp_m * 32 + mf * 16 + grp;
                ah[mf][0] = Ah[k + tig][mb];     al[mf][0] = Al[k + tig][mb];
                ah[mf][1] = Ah[k + tig][mb + 8]; al[mf][1] = Al[k + tig][mb + 8];
                ah[mf][2] = Ah[k + tig + 4][mb];     al[mf][2] = Al[k + tig + 4][mb];
                ah[mf][3] = Ah[k + tig + 4][mb + 8]; al[mf][3] = Al[k + tig + 4][mb + 8];
            }
#pragma unroll
            for (int nf = 0; nf < 4; ++nf) {
                int n = warp_n * 32 + nf * 8 + grp;
                unsigned bh0 = Bh[k + tig][n], bh1 = Bh[k + tig + 4][n];
                unsigned bl0 = Bl[k + tig][n], bl1 = Bl[k + tig + 4][n];
#pragma unroll
                for (int mf = 0; mf < 2; ++mf) {
                    mma8(acc[mf][nf], ah[mf][0], ah[mf][1], ah[mf][2], ah[mf][3], bh0, bh1);
                    mma8(acc[mf][nf], al[mf][0], al[mf][1], al[mf][2], al[mf][3], bh0, bh1);
                    mma8(acc[mf][nf], ah[mf][0], ah[mf][1], ah[mf][2], ah[mf][3], bl0, bl1);
                }
            }
        }
        __syncthreads();
    }

    // ---- store C ----
#pragma unroll
    for (int mf = 0; mf < 2; ++mf) {
        int r0 = m0 + warp_m * 32 + mf * 16 + grp;
        int r1 = r0 + 8;
#pragma unroll
        for (int nf = 0; nf < 4; ++nf) {
            int c = n0 + warp_n * 32 + nf * 8 + tig * 2;
            if (r0 < M)
                *(float2*)&C[(size_t)r0 * ldc + c] = make_float2(acc[mf][nf][0], acc[mf][nf][1]);
            if (r1 < M)
                *(float2*)&C[(size_t)r1 * ldc + c] = make_float2(acc[mf][nf][2], acc[mf][nf][3]);
        }
    }

    // ---- fused attention dots: head = n0/32 + warp_n (32 cols per warp) ----
    if (a_src != nullptr) {
        const int head = (n0 >> 5) + warp_n;
#pragma unroll
        for (int mf = 0; mf < 2; ++mf) {
            float ps0 = 0.f, pd0 = 0.f, ps1 = 0.f, pd1 = 0.f;
#pragma unroll
            for (int nf = 0; nf < 4; ++nf) {
                int cl = warp_n * 32 + nf * 8 + tig * 2;
                float w0s = sAs[cl], w1s = sAs[cl + 1];
                float w0d = sAd[cl], w1d = sAd[cl + 1];
                ps0 += acc[mf][nf][0] * w0s + acc[mf][nf][1] * w1s;
                pd0 += acc[mf][nf][0] * w0d + acc[mf][nf][1] * w1d;
                ps1 += acc[mf][nf][2] * w0s + acc[mf][nf][3] * w1s;
                pd1 += acc[mf][nf][2] * w0d + acc[mf][nf][3] * w1d;
            }
#pragma unroll
            for (int off = 1; off <= 2; off <<= 1) {
                ps0 += __shfl_xor_sync(0xffffffffu, ps0, off);
                pd0 += __shfl_xor_sync(0xffffffffu, pd0, off);
                ps1 += __shfl_xor_sync(0xffffffffu, ps1, off);
                pd1 += __shfl_xor_sync(0xffffffffu, pd1, off);
            }
            if (tig == 0) {
                int r0 = m0 + warp_m * 32 + mf * 16 + grp;
                int r1 = r0 + 8;
                if (r0 < M) { g_asrc[r0 * 8 + head] = ps0; g_adst[r0 * 8 + head] = pd0; }
                if (r1 < M) { g_asrc[r1 * 8 + head] = ps1; g_adst[r1 * 8 + head] = pd1; }
            }
        }
    }
}

// ---------------- CSR build ----------------
__global__ __launch_bounds__(256) void zero_cnt_kernel()
{
    int i = blockIdx.x * blockDim.x + threadIdx.x;
    if (i < N_NODES) g_cnt[i] = 0;
}
__global__ __launch_bounds__(256) void count_kernel(const int* __restrict__ ei)
{
    int e = blockIdx.x * blockDim.x + threadIdx.x;
    if (e < N_EDGES) atomicAdd(&g_cnt[ei[N_EDGES + e]], 1);
}
__global__ __launch_bounds__(256) void scan1_kernel()
{
    __shared__ int sh[256];
    int i = blockIdx.x * 256 + threadIdx.x;
    int v = (i < N_NODES) ? g_cnt[i] : 0;
    sh[threadIdx.x] = v;
    __syncthreads();
#pragma unroll
    for (int off = 1; off < 256; off <<= 1) {
        int t = 0;
        if (threadIdx.x >= off) t = sh[threadIdx.x - off];
        __syncthreads();
        if (threadIdx.x >= off) sh[threadIdx.x] += t;
        __syncthreads();
    }
    if (i < N_NODES) g_off[i + 1] = sh[threadIdx.x];
    if (threadIdx.x == 255) g_bsum[blockIdx.x] = sh[255];
    if (i == 0) g_off[0] = 0;
}
__global__ __launch_bounds__(256) void scan2_kernel(int nblocks)
{
    __shared__ int sh[256];
    int t = threadIdx.x;
    int v = (t < nblocks) ? g_bsum[t] : 0;
    sh[t] = v;
    __syncthreads();
#pragma unroll
    for (int off = 1; off < 256; off <<= 1) {
        int u = 0;
        if (t >= off) u = sh[t - off];
        __syncthreads();
        if (t >= off) sh[t] += u;
        __syncthreads();
    }
    if (t < nblocks) g_bsum[t] = sh[t] - v;    // exclusive
}
__global__ __launch_bounds__(256) void scan3_kernel()
{
    int i = blockIdx.x * 256 + threadIdx.x;
    if (i < N_NODES) g_off[i + 1] += g_bsum[blockIdx.x];
}
__global__ __launch_bounds__(256) void fillcpy_kernel()
{
    int i = blockIdx.x * blockDim.x + threadIdx.x;
    if (i < N_NODES) g_fill[i] = g_off[i];
}
__global__ __launch_bounds__(256) void scatter_kernel(const int* __restrict__ ei)
{
    int e = blockIdx.x * blockDim.x + threadIdx.x;
    if (e >= N_EDGES) return;
    int s = ei[e], d = ei[N_EDGES + e];
    int pos = atomicAdd(&g_fill[d], 1);
    g_csrc[pos] = s;
}

// -------- gather attention: one warp per node, fused softmax+agg+relu ------
__global__ __launch_bounds__(256) void gat_gather_kernel(const float* __restrict__ b)
{
    const int warp = threadIdx.x >> 5, lane = threadIdx.x & 31;
    const int n = blockIdx.x * 8 + warp;
    if (n >= N_NODES) return;
    const unsigned FULL = 0xffffffffu;
    const int h0 = lane >> 3, h1 = 4 + (lane >> 3);

    float myasrc = 0.f, myadst = 0.f;
    if (lane < 8) {
        myasrc = g_asrc[n * 8 + lane];
        myadst = g_adst[n * 8 + lane];
    }
    float4 acc0 = make_float4(0.f, 0.f, 0.f, 0.f);
    float4 acc1 = make_float4(0.f, 0.f, 0.f, 0.f);
    float denom = 0.f;

    const int beg = g_off[n], end = g_off[n + 1];
    for (int i = beg; i < end; ++i) {
        int s = g_csrc[i];
        float w = 0.f;
        if (lane < 8) {
            w = expf(leaky(g_asrc[s * 8 + lane] + myadst));
            denom += w;
        }
        float al0 = __shfl_sync(FULL, w, h0);
        float al1 = __shfl_sync(FULL, w, h1);
        float4 v0 = *(const float4*)&g_h[(size_t)s * 256 + lane * 4];
        float4 v1 = *(const float4*)&g_h[(size_t)s * 256 + 128 + lane * 4];
        acc0.x += al0 * v0.x; acc0.y += al0 * v0.y;
        acc0.z += al0 * v0.z; acc0.w += al0 * v0.w;
        acc1.x += al1 * v1.x; acc1.y += al1 * v1.y;
        acc1.z += al1 * v1.z; acc1.w += al1 * v1.w;
    }
    // self loop
    {
        float w = 0.f;
        if (lane < 8) {
            w = expf(leaky(myasrc + myadst));
            denom += w;
        }
        float al0 = __shfl_sync(FULL, w, h0);
        float al1 = __shfl_sync(FULL, w, h1);
        float4 v0 = *(const float4*)&g_h[(size_t)n * 256 + lane * 4];
        float4 v1 = *(const float4*)&g_h[(size_t)n * 256 + 128 + lane * 4];
        acc0.x += al0 * v0.x; acc0.y += al0 * v0.y;
        acc0.z += al0 * v0.z; acc0.w += al0 * v0.w;
        acc1.x += al1 * v1.x; acc1.y += al1 * v1.y;
        acc1.z += al1 * v1.z; acc1.w += al1 * v1.w;
    }
    float inv0 = 1.f / __shfl_sync(FULL, denom, h0);
    float inv1 = 1.f / __shfl_sync(FULL, denom, h1);
    float4 bb0 = *(const float4*)&b[lane * 4];
    float4 bb1 = *(const float4*)&b[128 + lane * 4];
    float4 o0, o1;
    o0.x = fmaxf(acc0.x * inv0 + bb0.x, 0.f);
    o0.y = fmaxf(acc0.y * inv0 + bb0.y, 0.f);
    o0.z = fmaxf(acc0.z * inv0 + bb0.z, 0.f);
    o0.w = fmaxf(acc0.w * inv0 + bb0.w, 0.f);
    o1.x = fmaxf(acc1.x * inv1 + bb1.x, 0.f);
    o1.y = fmaxf(acc1.y * inv1 + bb1.y, 0.f);
    o1.z = fmaxf(acc1.z * inv1 + bb1.z, 0.f);
    o1.w = fmaxf(acc1.w * inv1 + bb1.w, 0.f);
    *(float4*)&g_x[(size_t)n * 256 + lane * 4] = o0;
    *(float4*)&g_x[(size_t)n * 256 + 128 + lane * 4] = o1;
}

// ---------------- pack Wcat = [Wp1_a | Wp1_b] : [256 x 64] ----------------
__global__ __launch_bounds__(256) void pack_wcat_kernel(const float* __restrict__ Wp1)
{
    int i = blockIdx.x * blockDim.x + threadIdx.x;
    if (i >= 256 * 64) return;
    int k = i >> 6, j = i & 63;
    g_wcat[i] = (j < 32) ? Wp1[k * 32 + j] : Wp1[(256 + k) * 32 + (j - 32)];
}

// ---------------- edge predictor: emb MLP + combine (fp32) ----------------
__global__ __launch_bounds__(128) void edge_pred_kernel(
    const int* __restrict__ ei, const float* __restrict__ edge_attr,
    const float* __restrict__ Wm1, const float* __restrict__ bm1,
    const float* __restrict__ Wm2, const float* __restrict__ bm2,
    const float* __restrict__ Wp1, const float* __restrict__ bp1,
    const float* __restrict__ Wp2, const float* __restrict__ bp2,
    float* __restrict__ out)
{
    __shared__ float sEA[64 * 33];
    __shared__ float sT1[64 * 33];
    __shared__ float sW[3072];          // Wm1 | Wm2 | Wp1_c
    __shared__ int   sRow[64], sCol[64];
    __shared__ float sB[64];            // bm1 | bm2

    const int tid = threadIdx.x;
    const int tx = tid & 7;
    const int ey = tid >> 3;
    const int e0 = blockIdx.x * 64;

    if (tid < 64) {
        sRow[tid] = ei[e0 + tid];
        sCol[tid] = ei[N_EDGES + e0 + tid];
    }
    for (int i = tid; i < 3072; i += 128)
        sW[i] = (i < 1024) ? Wm1[i]
              : (i < 2048) ? Wm2[i - 1024]
                           : Wp1[512 * 32 + (i - 2048)];
    if (tid < 32) { sB[tid] = bm1[tid]; sB[32 + tid] = bm2[tid]; }
    for (int f = tid; f < 64 * 8; f += 128) {
        int e = f >> 3, q = f & 7;
        float4 v = *(const float4*)&edge_attr[(size_t)(e0 + e) * 32 + q * 4];
        float* p = &sEA[e * 33 + q * 4];
        p[0] = v.x; p[1] = v.y; p[2] = v.z; p[3] = v.w;
    }
    __syncthreads();

    // layer 1: T1 = relu(EA @ Wm1 + bm1)
    {
        float acc[4][4];
#pragma unroll
        for (int i = 0; i < 4; ++i)
#pragma unroll
            for (int j = 0; j < 4; ++j) acc[i][j] = 0.f;
#pragma unroll
        for (int k = 0; k < 32; ++k) {
            float4 w = *(const float4*)&sW[k * 32 + tx * 4];
#pragma unroll
            for (int i = 0; i < 4; ++i) {
                float a = sEA[(ey * 4 + i) * 33 + k];
                acc[i][0] += a * w.x; acc[i][1] += a * w.y;
                acc[i][2] += a * w.z; acc[i][3] += a * w.w;
            }
        }
#pragma unroll
        for (int i = 0; i < 4; ++i)
#pragma unroll
            for (int j = 0; j < 4; ++j) {
                float v = acc[i][j] + sB[tx * 4 + j];
                sT1[(ey * 4 + i) * 33 + tx * 4 + j] = v > 0.f ? v : 0.f;
            }
    }
    __syncthreads();
    // layer 2: EMB = relu(T1 @ Wm2 + bm2) -> sEA (reuse)
    {
        float acc[4][4];
#pragma unroll
        for (int i = 0; i < 4; ++i)
#pragma unroll
            for (int j = 0; j < 4; ++j) acc[i][j] = 0.f;
#pragma unroll
        for (int k = 0; k < 32; ++k) {
            float4 w = *(const float4*)&sW[1024 + k * 32 + tx * 4];
#pragma unroll
            for (int i = 0; i < 4; ++i) {
                float a = sT1[(ey * 4 + i) * 33 + k];
                acc[i][0] += a * w.x; acc[i][1] += a * w.y;
                acc[i][2] += a * w.z; acc[i][3] += a * w.w;
            }
        }
        __syncthreads();
#pragma unroll
        for (int i = 0; i < 4; ++i)
#pragma unroll
            for (int j = 0; j < 4; ++j) {
                float v = acc[i][j] + sB[32 + tx * 4 + j];
                sEA[(ey * 4 + i) * 33 + tx * 4 + j] = v > 0.f ? v : 0.f;
            }
    }
    __syncthreads();
    // layer 3: acc = EMB @ Wp1_c
    float acc[4][4];
#pragma unroll
    for (int i = 0; i < 4; ++i)
#pragma unroll
        for (int j = 0; j < 4; ++j) acc[i][j] = 0.f;
#pragma unroll
    for (int k = 0; k < 32; ++k) {
        float4 w = *(const float4*)&sW[2048 + k * 32 + tx * 4];
#pragma unroll
        for (int i = 0; i < 4; ++i) {
            float a = sEA[(ey * 4 + i) * 33 + k];
            acc[i][0] += a * w.x; acc[i][1] += a * w.y;
            acc[i][2] += a * w.z; acc[i][3] += a * w.w;
        }
    }

    // epilogue: pre = acc + P_a[row] + P_b[col] + bp1; out = relu(pre)@Wp2 + bp2
    float4 bp = *(const float4*)&bp1[tx * 4];
    float4 wp = *(const float4*)&Wp2[tx * 4];
    float bias2 = bp2[0];
#pragma unroll
    for (int i = 0; i < 4; ++i) {
        int e = ey * 4 + i;
        int r = sRow[e], c = sCol[e];
        float4 pa = *(const float4*)&g_p[(size_t)r * 64 + tx * 4];
        float4 pb = *(const float4*)&g_p[(size_t)c * 64 + 32 + tx * 4];
        float h0 = acc[i][0] + pa.x + pb.x + bp.x; h0 = h0 > 0.f ? h0 : 0.f;
        float h1 = acc[i][1] + pa.y + pb.y + bp.y; h1 = h1 > 0.f ? h1 : 0.f;
        float h2 = acc[i][2] + pa.z + pb.z + bp.z; h2 = h2 > 0.f ? h2 : 0.f;
        float h3 = acc[i][3] + pa.w + pb.w + bp.w; h3 = h3 > 0.f ? h3 : 0.f;
        float p = h0 * wp.x + h1 * wp.y + h2 * wp.z + h3 * wp.w;
        p += __shfl_down_sync(0xffffffffu, p, 4, 8);
        p += __shfl_down_sync(0xffffffffu, p, 2, 8);
        p += __shfl_down_sync(0xffffffffu, p, 1, 8);
        if (tx == 0) out[e0 + e] = p + bias2;
    }
}

// ---------------- host ----------------
extern "C" void kernel_launch(void* const* d_in, const int* in_sizes, int n_in,
                              void* d_out, int out_size)
{
    const float* x   = (const float*)d_in[0];
    const int*   ei  = (const int*)d_in[1];
    const float* ea  = (const float*)d_in[2];
    const float* W1  = (const float*)d_in[3];
    const float* as1 = (const float*)d_in[4];
    const float* ad1 = (const float*)d_in[5];
    const float* b1  = (const float*)d_in[6];
    const float* W2  = (const float*)d_in[7];
    const float* as2 = (const float*)d_in[8];
    const float* ad2 = (const float*)d_in[9];
    const float* b2  = (const float*)d_in[10];
    const float* Wm1 = (const float*)d_in[11];
    const float* bm1 = (const float*)d_in[12];
    const float* Wm2 = (const float*)d_in[13];
    const float* bm2 = (const float*)d_in[14];
    const float* Wp1 = (const float*)d_in[15];
    const float* bp1 = (const float*)d_in[16];
    const float* Wp2 = (const float*)d_in[17];
    const float* bp2 = (const float*)d_in[18];
    float* out = (float*)d_out;

    float *ph = nullptr, *px = nullptr, *pw = nullptr, *pp = nullptr;
    cudaGetSymbolAddress((void**)&ph, g_h);
    cudaGetSymbolAddress((void**)&px, g_x);
    cudaGetSymbolAddress((void**)&pw, g_wcat);
    cudaGetSymbolAddress((void**)&pp, g_p);

    const int EB  = (N_EDGES + 255) / 256;
    const int NB  = (N_NODES + 255) / 256;
    const int NWB = (N_NODES + 7) / 8;

    // ---- CSR build (once; reused by both layers) ----
    zero_cnt_kernel<<<NB, 256>>>();
    count_kernel<<<EB, 256>>>(ei);
    scan1_kernel<<<NB, 256>>>();
    scan2_kernel<<<1, 256>>>(NB);
    scan3_kernel<<<NB, 256>>>();
    fillcpy_kernel<<<NB, 256>>>();
    scatter_kernel<<<EB, 256>>>(ei);

    for (int layer = 0; layer < 2; ++layer) {
        const float* X   = layer ? px : x;
        const int    K   = layer ? 256 : 128;
        const float* W   = layer ? W2 : W1;
        const float* as_ = layer ? as2 : as1;
        const float* ad_ = layer ? ad2 : ad1;
        const float* b_  = layer ? b2 : b1;

        tc_gemm_kernel<<<dim3(391, 4), 256>>>(X, W, ph, N_NODES, K, 256, 256, as_, ad_);
        gat_gather_kernel<<<NWB, 256>>>(b_);
    }
    pack_wcat_kernel<<<64, 256>>>(Wp1);
    tc_gemm_kernel<<<dim3(391, 1), 256>>>(px, pw, pp, N_NODES, 256, 64, 64,
                                          nullptr, nullptr);
    edge_pred_kernel<<<N_EDGES / 64, 128>>>(ei, ea,
                                            Wm1, bm1, Wm2, bm2,
                                            Wp1, bp1, Wp2, bp2, out);
}